// round 8
// baseline (speedup 1.0000x reference)
#include <cuda_runtime.h>

#define Bdim 256
#define Sdim 512
#define Fdim 64
#define Hdim 128
#define BS   (Bdim * Sdim)
#define NBLK 64            // 4 batch rows per block
#define KQ   28            // streamed Whh quad groups (k = 16..127)

__device__ float g_invDenom[Sdim];
__device__ float g_lossPartial[NBLK];
__device__ float g_WhhQ[KQ * 512 * 4];            // [(q*512+j)*4+r] = Whh[j][16+4q+r]
__device__ float g_gh[(size_t)BS * Hdim];         // gamma_h
__device__ float g_beta[(size_t)BS * Fdim];       // beta
__device__ float g_gml[(size_t)BS * 512];         // [b][s][j]: ml@WihMask^T + bio

typedef unsigned long long u64;
__device__ __forceinline__ u64 pk2(float lo, float hi) {
    u64 r; asm("mov.b64 %0,{%1,%2};" : "=l"(r) : "r"(__float_as_uint(lo)), "r"(__float_as_uint(hi))); return r;
}
__device__ __forceinline__ void up2(u64 v, float& lo, float& hi) {
    unsigned a, b; asm("mov.b64 {%0,%1},%2;" : "=r"(a), "=r"(b) : "l"(v));
    lo = __uint_as_float(a); hi = __uint_as_float(b);
}
__device__ __forceinline__ u64 ff2(u64 a, u64 b, u64 c) {
    u64 d; asm("fma.rn.f32x2 %0,%1,%2,%3;" : "=l"(d) : "l"(a), "l"(b), "l"(c)); return d;
}
__device__ __forceinline__ float sigf(float v) { return 1.f / (1.f + expf(-v)); }

// ---------- per-step 1/(sum(m)+1e-5) ----------
__global__ void rits_denom(const float* __restrict__ m) {
    __shared__ float red[256];
    const int s = blockIdx.x, t = threadIdx.x;
    const float4* p = (const float4*)(m + (size_t)t * Sdim * Fdim + (size_t)s * Fdim);
    float sum = 0.f;
#pragma unroll
    for (int i = 0; i < 16; ++i) { float4 v = p[i]; sum += v.x + v.y + v.z + v.w; }
    red[t] = sum;
    __syncthreads();
    for (int off = 128; off > 0; off >>= 1) { if (t < off) red[t] += red[t + off]; __syncthreads(); }
    if (t == 0) g_invDenom[s] = 1.0f / (red[0] + 1e-5f);
}

// ---------- Whh streamed-tail swizzle (k = 16..127) ----------
__global__ void rits_whhq(const float* __restrict__ Whh) {
    const int i = blockIdx.x * 256 + threadIdx.x;
    if (i < KQ * 512 * 4) {
        const int r = i & 3, j = (i >> 2) & 511, q = i >> 11;
        g_WhhQ[i] = Whh[j * Hdim + 16 + 4 * q + r];
    }
}

// ---------- gamma_h (double-buffered, grid 1024) ----------
__global__ __launch_bounds__(256) void rits_gh(const float* __restrict__ tt,
                                               const float* __restrict__ Wdh,
                                               const float* __restrict__ bdh) {
    __shared__ float w[Fdim * Hdim];
    __shared__ float bb[Hdim], tl[2][128];
    const int t = threadIdx.x;
    for (int i = t; i < Fdim * Hdim; i += 256) { const int k = i >> 7, h = i & 127; w[i] = Wdh[h * Fdim + k]; }
    if (t < Hdim) bb[t] = bdh[t];
    const int rr = t >> 7, h = t & 127;
    const size_t base = (size_t)blockIdx.x * 128;
    float v = 0.f;
    if (t < 128) v = tt[(base + (t >> 6)) * Fdim + (t & 63)];
    __syncthreads();
    for (int it = 0; it < 64; ++it) {
        const size_t rs = base + it * 2;
        if (t < 128) tl[it & 1][t] = v;
        __syncthreads();
        if (t < 128 && it < 63) v = tt[(rs + 2 + (t >> 6)) * Fdim + (t & 63)];
        float a0 = 0.f, a1 = 0.f;
        const float* tlr = tl[it & 1] + rr * 64;
#pragma unroll 8
        for (int k = 0; k < Fdim; k += 2) { a0 += tlr[k] * w[k * 128 + h]; a1 += tlr[k + 1] * w[(k + 1) * 128 + h]; }
        g_gh[(rs + rr) * Hdim + h] = expf(-fmaxf(a0 + a1 + bb[h], 0.f));
    }
}

// ---------- beta (double-buffered, grid 1024) ----------
__global__ __launch_bounds__(256) void rits_betak(const float* __restrict__ tt, const float* __restrict__ m,
                                                  const float* __restrict__ Wdm, const float* __restrict__ bdm,
                                                  const float* __restrict__ Wwc, const float* __restrict__ bwc) {
    __shared__ float w[128 * Fdim];
    __shared__ float dwdm[64], cb[64], cw[64], gm[2][256], ms[2][256];
    const int t = threadIdx.x;
    for (int i = t; i < 128 * Fdim; i += 256) { const int k = i >> 6, f = i & 63; w[i] = Wwc[f * 128 + k]; }
    if (t < 64) { dwdm[t] = Wdm[t * Fdim + t]; cb[t] = bdm[t]; cw[t] = bwc[t]; }
    const int r = t >> 6, f = t & 63;
    const size_t base = (size_t)blockIdx.x * 128;
    float vt = tt[(base + r) * Fdim + f], vm = m[(base + r) * Fdim + f];
    __syncthreads();
    for (int it = 0; it < 32; ++it) {
        const size_t rs = base + it * 4 + r;
        const int bf = it & 1;
        gm[bf][t] = expf(-fmaxf(vt * dwdm[f] + cb[f], 0.f)); ms[bf][t] = vm;
        __syncthreads();
        if (it < 31) { vt = tt[(rs + 4) * Fdim + f]; vm = m[(rs + 4) * Fdim + f]; }
        float a0 = cw[f], a1 = 0.f;
        const float* gr = gm[bf] + r * 64; const float* mr = ms[bf] + r * 64;
#pragma unroll 8
        for (int k = 0; k < 64; ++k) { a0 += gr[k] * w[k * 64 + f]; a1 += mr[k] * w[(64 + k) * 64 + f]; }
        g_beta[rs * Fdim + f] = a0 + a1;
    }
}

// ---------- gml = ml @ WihMask^T + bih + bhh (grid 512, double-buffered) ----------
#define GML_SMF (32768 + 512 + 512)
__global__ __launch_bounds__(256, 1) void rits_gml(const float* __restrict__ m, const float* __restrict__ Wih,
                                                   const float* __restrict__ bih, const float* __restrict__ bhh) {
    extern __shared__ float sg[];
    float* WT  = sg;            // [(k2*512+j)*2+r] = Wih[j][64+2k2+r]
    float* BIO = sg + 32768;
    float* MLP = sg + 33280;    // [2 buf][2 pair][128]
    const int t = threadIdx.x;
    for (int i = t; i < 32768; i += 256) { const int r = i & 1, j = (i >> 1) & 511, k2 = i >> 10; WT[i] = Wih[j * 128 + 64 + 2 * k2 + r]; }
    for (int i = t; i < 512; i += 256) BIO[i] = bih[i] + bhh[i];
    const int j0 = t, j1 = t + 256;
    const int pr = t >> 7, gq = (t >> 6) & 1, f = t & 63;
    const size_t base = (size_t)blockIdx.x * 128;   // 128 p per block (2 per iter)
    float v;
    { const size_t p0 = base; const size_t bp = p0 >> 9; const int s0 = (int)(p0 & 511);
      v = m[((2 * bp + gq) * Sdim + s0 + pr) * Fdim + f]; }
    __syncthreads();
    for (int it = 0; it < 64; ++it) {
        const size_t p0 = base + 2 * it; const size_t bp = p0 >> 9; const int s0 = (int)(p0 & 511);
        float* B = MLP + (it & 1) * 256;
        B[pr * 128 + 2 * f + gq] = v;
        __syncthreads();
        if (it < 63) { const size_t pn = base + 2 * (it + 1); const size_t bpn = pn >> 9; const int sn0 = (int)(pn & 511);
            v = m[((2 * bpn + gq) * Sdim + sn0 + pr) * Fdim + f]; }
        const float bj0 = BIO[j0], bj1 = BIO[j1];
        u64 a00 = pk2(bj0, bj0), a01 = pk2(bj0, bj0);
        u64 a10 = pk2(bj1, bj1), a11 = pk2(bj1, bj1);
        const float* B0 = B; const float* B1 = B + 128;
#pragma unroll 8
        for (int k2 = 0; k2 < 32; ++k2) {
            const float2 w0 = *(const float2*)(WT + (k2 * 512 + j0) * 2);
            const float2 w1 = *(const float2*)(WT + (k2 * 512 + j1) * 2);
            const ulonglong2 q0 = *(const ulonglong2*)(B0 + 4 * k2);
            const ulonglong2 q1 = *(const ulonglong2*)(B1 + 4 * k2);
            const u64 wx0 = pk2(w0.x, w0.x), wy0 = pk2(w0.y, w0.y);
            const u64 wx1 = pk2(w1.x, w1.x), wy1 = pk2(w1.y, w1.y);
            a00 = ff2(wx0, q0.x, a00); a00 = ff2(wy0, q0.y, a00);
            a01 = ff2(wx0, q1.x, a01); a01 = ff2(wy0, q1.y, a01);
            a10 = ff2(wx1, q0.x, a10); a10 = ff2(wy1, q0.y, a10);
            a11 = ff2(wx1, q1.x, a11); a11 = ff2(wy1, q1.y, a11);
        }
        float lo, hi;
        up2(a00, lo, hi);
        g_gml[((2 * bp + 0) * Sdim + s0) * 512 + j0] = lo;
        g_gml[((2 * bp + 1) * Sdim + s0) * 512 + j0] = hi;
        up2(a01, lo, hi);
        g_gml[((2 * bp + 0) * Sdim + s0 + 1) * 512 + j0] = lo;
        g_gml[((2 * bp + 1) * Sdim + s0 + 1) * 512 + j0] = hi;
        up2(a10, lo, hi);
        g_gml[((2 * bp + 0) * Sdim + s0) * 512 + j1] = lo;
        g_gml[((2 * bp + 1) * Sdim + s0) * 512 + j1] = hi;
        up2(a11, lo, hi);
        g_gml[((2 * bp + 0) * Sdim + s0 + 1) * 512 + j1] = lo;
        g_gml[((2 * bp + 1) * Sdim + s0 + 1) * 512 + j1] = hi;
    }
}

// ---------- main sequential kernel (G=4 rows, 512 threads, 1 j-col/thread) ----------
#define M_WIHQ 0        // 32768: [q<16][j][4] = Wih[j][4q+r]
#define M_WHHR 32768    // 8192:  [q<4][j][4]  = Whh[j][4q+r]
#define M_WTRQ 40960    // 8192:  [q<32][f][4] = Wtr[f][4q+r]
#define M_WFRQ 49152    // 4096:  [q<16][f][4] = Wfr_m[f][4q+r]
#define M_HR   53248    // 512:  hRow[4][128]
#define M_XC   53760    // 256:  xcRow[4][64]
#define M_CLC  54016    // 256:  clcRow[4][64]
#define M_GT   54272    // 2048: gates[4][512]
#define M_BTR  56320
#define M_BFR  56384
#define M_RED  56448    // 512
#define M_SMF  56960
#define M_SMB  (M_SMF * 4)   // 227,840 B

// one quad-k group for one j-column, 4 rows: 5 loads, 8 ff2, 0 packing
#define FQ(WPTR, APTR, STR) do {                                        \
    const ulonglong2 w_ = *(const ulonglong2*)(WPTR);                   \
    { const ulonglong2 a_ = *(const ulonglong2*)(APTR);                 \
      A0 = ff2(w_.x, a_.x, A0); A0 = ff2(w_.y, a_.y, A0); }             \
    { const ulonglong2 a_ = *(const ulonglong2*)((APTR) + (STR));       \
      A1 = ff2(w_.x, a_.x, A1); A1 = ff2(w_.y, a_.y, A1); }             \
    { const ulonglong2 a_ = *(const ulonglong2*)((APTR) + 2 * (STR));   \
      A2 = ff2(w_.x, a_.x, A2); A2 = ff2(w_.y, a_.y, A2); }             \
    { const ulonglong2 a_ = *(const ulonglong2*)((APTR) + 3 * (STR));   \
      A3 = ff2(w_.x, a_.x, A3); A3 = ff2(w_.y, a_.y, A3); }             \
} while (0)

__global__ __launch_bounds__(512, 1) void rits_main(
    const float* __restrict__ x, const float* __restrict__ m,
    const float* __restrict__ Wtr, const float* __restrict__ btr,
    const float* __restrict__ Wfr, const float* __restrict__ bfr,
    const float* __restrict__ Wih, const float* __restrict__ Whh,
    float* __restrict__ out)
{
    extern __shared__ float sm[];
    const int t = threadIdx.x;
    const int b0 = blockIdx.x * 4;

    for (int i = t; i < 32768; i += 512) { const int r = i & 3, j = (i >> 2) & 511, q = i >> 11; sm[M_WIHQ + i] = Wih[j * 128 + 4 * q + r]; }
    for (int i = t; i < 8192; i += 512)  { const int r = i & 3, j = (i >> 2) & 511, q = i >> 11; sm[M_WHHR + i] = Whh[j * 128 + 4 * q + r]; }
    for (int i = t; i < 8192; i += 512)  { const int r = i & 3, f = (i >> 2) & 63, q = i >> 8; sm[M_WTRQ + i] = Wtr[f * 128 + 4 * q + r]; }
    for (int i = t; i < 4096; i += 512)  { const int r = i & 3, f = (i >> 2) & 63, q = i >> 8; const int k = 4 * q + r; sm[M_WFRQ + i] = (k == f) ? 0.f : Wfr[f * 64 + k]; }
    if (t < 64) { sm[M_BTR + t] = btr[t]; sm[M_BFR + t] = bfr[t]; }
    for (int i = t; i < 512; i += 512) sm[M_HR + i] = 0.f;
    float c_reg = 0.f, loss = 0.f;

    const int rE = t >> 6, fE = t & 63;     // C/D/E role (t < 256)
    const int jF = t;                       // F role: one gate column
    const int rG = t >> 7, jG = t & 127;    // G role: one LSTM state

    // prologue prefetch (s = 0)
    float cx = 0.f, cm = 0.f, cbeta = 0.f;
    if (t < 256) {
        const size_t idxP = ((size_t)(b0 + rE) * Sdim) * Fdim + fE;
        cx = x[idxP]; cm = m[idxP]; cbeta = g_beta[idxP];
    }
    float cgml[4];
#pragma unroll
    for (int r = 0; r < 4; ++r) cgml[r] = g_gml[((size_t)(b0 + r) * Sdim) * 512 + jF];
    __syncthreads();

    for (int s = 0; s < Sdim; ++s) {
        const int sn = (s < Sdim - 1) ? s + 1 : s;
        // prefetch: gamma_h(s+1) for G; next-step x/m/beta/gml
        const float ghv = g_gh[((size_t)(b0 + rG) * Sdim + sn) * Hdim + jG];
        float nx = 0.f, nm = 0.f, nbeta = 0.f, cInv = 0.f;
        if (t < 256) {
            cInv = g_invDenom[s];
            const size_t idxN = ((size_t)(b0 + rE) * Sdim + sn) * Fdim + fE;
            nx = x[idxN]; nm = m[idxN]; nbeta = g_beta[idxN];
        }
        float ngml[4];
#pragma unroll
        for (int r = 0; r < 4; ++r) ngml[r] = g_gml[((size_t)(b0 + r) * Sdim + sn) * 512 + jF];

        // C: xl_hat = h @ Wtr^T + btr ; xl_c   (t < 256)
        float xh = 0.f;
        if (t < 256) {
            u64 acc = 0ULL;
            const float* hr = sm + M_HR + rE * 128;
#pragma unroll 8
            for (int q = 0; q < 32; ++q) {
                const ulonglong2 w = *(const ulonglong2*)(sm + M_WTRQ + (q * 64 + fE) * 4);
                const ulonglong2 a = *(const ulonglong2*)(hr + 4 * q);
                acc = ff2(w.x, a.x, acc); acc = ff2(w.y, a.y, acc);
            }
            float lo, hi; up2(acc, lo, hi);
            xh = sm[M_BTR + fE] + lo + hi;
            sm[M_XC + rE * 64 + fE] = cm * cx + (1.f - cm) * xh;
        }
        __syncthreads();

        // D+E: zl_hat, cl_hat, cl_c, output, loss   (t < 256)
        if (t < 256) {
            u64 acc = 0ULL;
            const float* xr = sm + M_XC + rE * 64;
#pragma unroll
            for (int q = 0; q < 16; ++q) {
                const ulonglong2 w = *(const ulonglong2*)(sm + M_WFRQ + (q * 64 + fE) * 4);
                const ulonglong2 a = *(const ulonglong2*)(xr + 4 * q);
                acc = ff2(w.x, a.x, acc); acc = ff2(w.y, a.y, acc);
            }
            float lo, hi; up2(acc, lo, hi);
            const float zh = sm[M_BFR + fE] + lo + hi;
            const float ch = cbeta * zh + (1.f - cbeta) * xh;
            const float cc = cm * cx + (1.f - cm) * ch;
            sm[M_CLC + rE * 64 + fE] = cc;
            out[((size_t)(b0 + rE) * Sdim + s) * Fdim + fE] = cc;
            const float d1 = cx - xh, d2 = cx - zh, d3 = cx - ch;
            loss += cm * (d1 * d1 + d2 * d2 + d3 * d3) * cInv;
        }
        __syncthreads();

        // F: gates[r][jF] = gml + clc @ WihClc^T + h @ Whh^T (all 512 threads)
        {
            u64 A0 = 0ULL, A1 = 0ULL, A2 = 0ULL, A3 = 0ULL;
#pragma unroll
            for (int q = 0; q < 16; ++q)
                FQ(sm + M_WIHQ + (q * 512 + jF) * 4, sm + M_CLC + 4 * q, 64);
#pragma unroll
            for (int q = 0; q < 4; ++q)
                FQ(sm + M_WHHR + (q * 512 + jF) * 4, sm + M_HR + 4 * q, 128);
#pragma unroll 7
            for (int q = 0; q < KQ; ++q)
                FQ(g_WhhQ + ((size_t)q * 512 + jF) * 4, sm + M_HR + 16 + 4 * q, 128);
            float lo, hi;
            up2(A0, lo, hi); sm[M_GT + 0 * 512 + jF] = lo + hi + cgml[0];
            up2(A1, lo, hi); sm[M_GT + 1 * 512 + jF] = lo + hi + cgml[1];
            up2(A2, lo, hi); sm[M_GT + 2 * 512 + jF] = lo + hi + cgml[2];
            up2(A3, lo, hi); sm[M_GT + 3 * 512 + jF] = lo + hi + cgml[3];
        }
        __syncthreads();

        // G: LSTM update + apply gamma_h(s+1)   (1 state per thread)
        {
            const float* gg = sm + M_GT + rG * 512;
            const float iv = sigf(gg[jG]);
            const float fv = sigf(gg[128 + jG]);
            const float gv = tanhf(gg[256 + jG]);
            const float ov = sigf(gg[384 + jG]);
            c_reg = fv * c_reg + iv * gv;
            sm[M_HR + rG * 128 + jG] = ov * tanhf(c_reg) * ghv;
        }
        __syncthreads();

        cx = nx; cm = nm; cbeta = nbeta;
#pragma unroll
        for (int r = 0; r < 4; ++r) cgml[r] = ngml[r];
    }

    sm[M_RED + t] = loss;
    __syncthreads();
    for (int off = 256; off > 0; off >>= 1) { if (t < off) sm[M_RED + t] += sm[M_RED + t + off]; __syncthreads(); }
    if (t == 0) g_lossPartial[blockIdx.x] = sm[M_RED];
}

__global__ void rits_loss_final(float* __restrict__ out, int out_size) {
    __shared__ float red[NBLK];
    const int t = threadIdx.x;
    red[t] = g_lossPartial[t];
    __syncthreads();
    for (int off = NBLK / 2; off > 0; off >>= 1) { if (t < off) red[t] += red[t + off]; __syncthreads(); }
    const long long bsf = (long long)Bdim * Sdim * Fdim;
    if (t == 0 && (long long)out_size > bsf) out[bsf] = red[0] / (float)Sdim;
}

extern "C" void kernel_launch(void* const* d_in, const int* in_sizes, int n_in,
                              void* d_out, int out_size) {
    const float* x   = (const float*)d_in[0];
    const float* m   = (const float*)d_in[1];
    const float* tt  = (const float*)d_in[2];
    const float* Wdh = (const float*)d_in[3];
    const float* bdh = (const float*)d_in[4];
    const float* Wdm = (const float*)d_in[5];
    const float* bdm = (const float*)d_in[6];
    const float* Wtr = (const float*)d_in[7];
    const float* btr = (const float*)d_in[8];
    const float* Wfr = (const float*)d_in[9];
    const float* bfr = (const float*)d_in[10];
    const float* Wwc = (const float*)d_in[11];
    const float* bwc = (const float*)d_in[12];
    const float* Wih = (const float*)d_in[13];
    const float* Whh = (const float*)d_in[14];
    const float* bih = (const float*)d_in[15];
    const float* bhh = (const float*)d_in[16];
    float* out = (float*)d_out;

    cudaFuncSetAttribute(rits_gml, cudaFuncAttributeMaxDynamicSharedMemorySize, GML_SMF * 4);
    cudaFuncSetAttribute(rits_main, cudaFuncAttributeMaxDynamicSharedMemorySize, M_SMB);

    rits_denom<<<Sdim, 256>>>(m);
    rits_whhq<<<(KQ * 512 * 4 + 255) / 256, 256>>>(Whh);
    rits_gh<<<1024, 256>>>(tt, Wdh, bdh);
    rits_betak<<<1024, 256>>>(tt, m, Wdm, bdm, Wwc, bwc);
    rits_gml<<<512, 256, GML_SMF * 4>>>(m, Wih, bih, bhh);
    rits_main<<<NBLK, 512, M_SMB>>>(x, m, Wtr, btr, Wfr, bfr, Wih, Whh, out);
    rits_loss_final<<<1, NBLK>>>(out, out_size);
}

// round 9
// speedup vs baseline: 1.4968x; 1.4968x over previous
#include <cuda_runtime.h>

#define Bdim 256
#define Sdim 512
#define Fdim 64
#define Hdim 128
#define BS   (Bdim * Sdim)
#define NBLK 128           // 2 batch rows per block
#define KQ   28            // streamed Whh quad groups (k = 16..127)

__device__ float g_invDenom[Sdim];
__device__ float g_lossPartial[NBLK];
__device__ float g_WhhQ[KQ * 512 * 4];            // [(q*512+j)*4+r] = Whh[j][16+4q+r]
__device__ float g_gh[(size_t)BS * Hdim];         // gamma_h
__device__ float g_beta[(size_t)BS * Fdim];       // beta
__device__ float g_gml[(size_t)BS * 512];         // [b][s][j]: ml@WihMask^T + bio

typedef unsigned long long u64;
__device__ __forceinline__ u64 pk2(float lo, float hi) {
    u64 r; asm("mov.b64 %0,{%1,%2};" : "=l"(r) : "r"(__float_as_uint(lo)), "r"(__float_as_uint(hi))); return r;
}
__device__ __forceinline__ void up2(u64 v, float& lo, float& hi) {
    unsigned a, b; asm("mov.b64 {%0,%1},%2;" : "=r"(a), "=r"(b) : "l"(v));
    lo = __uint_as_float(a); hi = __uint_as_float(b);
}
__device__ __forceinline__ u64 ff2(u64 a, u64 b, u64 c) {
    u64 d; asm("fma.rn.f32x2 %0,%1,%2,%3;" : "=l"(d) : "l"(a), "l"(b), "l"(c)); return d;
}
__device__ __forceinline__ float sigf(float v) { return 1.f / (1.f + expf(-v)); }

// ---------- per-step 1/(sum(m)+1e-5) ----------
__global__ void rits_denom(const float* __restrict__ m) {
    __shared__ float red[256];
    const int s = blockIdx.x, t = threadIdx.x;
    const float4* p = (const float4*)(m + (size_t)t * Sdim * Fdim + (size_t)s * Fdim);
    float sum = 0.f;
#pragma unroll
    for (int i = 0; i < 16; ++i) { float4 v = p[i]; sum += v.x + v.y + v.z + v.w; }
    red[t] = sum;
    __syncthreads();
    for (int off = 128; off > 0; off >>= 1) { if (t < off) red[t] += red[t + off]; __syncthreads(); }
    if (t == 0) g_invDenom[s] = 1.0f / (red[0] + 1e-5f);
}

// ---------- Whh streamed-tail swizzle (k = 16..127) ----------
__global__ void rits_whhq(const float* __restrict__ Whh) {
    const int i = blockIdx.x * 256 + threadIdx.x;
    if (i < KQ * 512 * 4) {
        const int r = i & 3, j = (i >> 2) & 511, q = i >> 11;
        g_WhhQ[i] = Whh[j * Hdim + 16 + 4 * q + r];
    }
}

// ---------- gamma_h (double-buffered, grid 1024) ----------
__global__ __launch_bounds__(256) void rits_gh(const float* __restrict__ tt,
                                               const float* __restrict__ Wdh,
                                               const float* __restrict__ bdh) {
    __shared__ float w[Fdim * Hdim];
    __shared__ float bb[Hdim], tl[2][128];
    const int t = threadIdx.x;
    for (int i = t; i < Fdim * Hdim; i += 256) { const int k = i >> 7, h = i & 127; w[i] = Wdh[h * Fdim + k]; }
    if (t < Hdim) bb[t] = bdh[t];
    const int rr = t >> 7, h = t & 127;
    const size_t base = (size_t)blockIdx.x * 128;
    float v = 0.f;
    if (t < 128) v = tt[(base + (t >> 6)) * Fdim + (t & 63)];
    __syncthreads();
    for (int it = 0; it < 64; ++it) {
        const size_t rs = base + it * 2;
        if (t < 128) tl[it & 1][t] = v;
        __syncthreads();
        if (t < 128 && it < 63) v = tt[(rs + 2 + (t >> 6)) * Fdim + (t & 63)];
        float a0 = 0.f, a1 = 0.f;
        const float* tlr = tl[it & 1] + rr * 64;
#pragma unroll 8
        for (int k = 0; k < Fdim; k += 2) { a0 += tlr[k] * w[k * 128 + h]; a1 += tlr[k + 1] * w[(k + 1) * 128 + h]; }
        g_gh[(rs + rr) * Hdim + h] = expf(-fmaxf(a0 + a1 + bb[h], 0.f));
    }
}

// ---------- beta (double-buffered, grid 1024) ----------
__global__ __launch_bounds__(256) void rits_betak(const float* __restrict__ tt, const float* __restrict__ m,
                                                  const float* __restrict__ Wdm, const float* __restrict__ bdm,
                                                  const float* __restrict__ Wwc, const float* __restrict__ bwc) {
    __shared__ float w[128 * Fdim];
    __shared__ float dwdm[64], cb[64], cw[64], gm[2][256], ms[2][256];
    const int t = threadIdx.x;
    for (int i = t; i < 128 * Fdim; i += 256) { const int k = i >> 6, f = i & 63; w[i] = Wwc[f * 128 + k]; }
    if (t < 64) { dwdm[t] = Wdm[t * Fdim + t]; cb[t] = bdm[t]; cw[t] = bwc[t]; }
    const int r = t >> 6, f = t & 63;
    const size_t base = (size_t)blockIdx.x * 128;
    float vt = tt[(base + r) * Fdim + f], vm = m[(base + r) * Fdim + f];
    __syncthreads();
    for (int it = 0; it < 32; ++it) {
        const size_t rs = base + it * 4 + r;
        const int bf = it & 1;
        gm[bf][t] = expf(-fmaxf(vt * dwdm[f] + cb[f], 0.f)); ms[bf][t] = vm;
        __syncthreads();
        if (it < 31) { vt = tt[(rs + 4) * Fdim + f]; vm = m[(rs + 4) * Fdim + f]; }
        float a0 = cw[f], a1 = 0.f;
        const float* gr = gm[bf] + r * 64; const float* mr = ms[bf] + r * 64;
#pragma unroll 8
        for (int k = 0; k < 64; ++k) { a0 += gr[k] * w[k * 64 + f]; a1 += mr[k] * w[(64 + k) * 64 + f]; }
        g_beta[rs * Fdim + f] = a0 + a1;
    }
}

// ---------- gml = ml @ WihMask^T + bih + bhh (grid 512, double-buffered) ----------
#define GML_SMF (32768 + 512 + 512)
__global__ __launch_bounds__(256, 1) void rits_gml(const float* __restrict__ m, const float* __restrict__ Wih,
                                                   const float* __restrict__ bih, const float* __restrict__ bhh) {
    extern __shared__ float sg[];
    float* WT  = sg;            // [(k2*512+j)*2+r] = Wih[j][64+2k2+r]
    float* BIO = sg + 32768;
    float* MLP = sg + 33280;    // [2 buf][2 pair][128]
    const int t = threadIdx.x;
    for (int i = t; i < 32768; i += 256) { const int r = i & 1, j = (i >> 1) & 511, k2 = i >> 10; WT[i] = Wih[j * 128 + 64 + 2 * k2 + r]; }
    for (int i = t; i < 512; i += 256) BIO[i] = bih[i] + bhh[i];
    const int j0 = t, j1 = t + 256;
    const int pr = t >> 7, gq = (t >> 6) & 1, f = t & 63;
    const size_t base = (size_t)blockIdx.x * 128;
    float v;
    { const size_t p0 = base; const size_t bp = p0 >> 9; const int s0 = (int)(p0 & 511);
      v = m[((2 * bp + gq) * Sdim + s0 + pr) * Fdim + f]; }
    __syncthreads();
    for (int it = 0; it < 64; ++it) {
        const size_t p0 = base + 2 * it; const size_t bp = p0 >> 9; const int s0 = (int)(p0 & 511);
        float* B = MLP + (it & 1) * 256;
        B[pr * 128 + 2 * f + gq] = v;
        __syncthreads();
        if (it < 63) { const size_t pn = base + 2 * (it + 1); const size_t bpn = pn >> 9; const int sn0 = (int)(pn & 511);
            v = m[((2 * bpn + gq) * Sdim + sn0 + pr) * Fdim + f]; }
        const float bj0 = BIO[j0], bj1 = BIO[j1];
        u64 a00 = pk2(bj0, bj0), a01 = pk2(bj0, bj0);
        u64 a10 = pk2(bj1, bj1), a11 = pk2(bj1, bj1);
        const float* B0 = B; const float* B1 = B + 128;
#pragma unroll 8
        for (int k2 = 0; k2 < 32; ++k2) {
            const float2 w0 = *(const float2*)(WT + (k2 * 512 + j0) * 2);
            const float2 w1 = *(const float2*)(WT + (k2 * 512 + j1) * 2);
            const ulonglong2 q0 = *(const ulonglong2*)(B0 + 4 * k2);
            const ulonglong2 q1 = *(const ulonglong2*)(B1 + 4 * k2);
            const u64 wx0 = pk2(w0.x, w0.x), wy0 = pk2(w0.y, w0.y);
            const u64 wx1 = pk2(w1.x, w1.x), wy1 = pk2(w1.y, w1.y);
            a00 = ff2(wx0, q0.x, a00); a00 = ff2(wy0, q0.y, a00);
            a01 = ff2(wx0, q1.x, a01); a01 = ff2(wy0, q1.y, a01);
            a10 = ff2(wx1, q0.x, a10); a10 = ff2(wy1, q0.y, a10);
            a11 = ff2(wx1, q1.x, a11); a11 = ff2(wy1, q1.y, a11);
        }
        float lo, hi;
        up2(a00, lo, hi);
        g_gml[((2 * bp + 0) * Sdim + s0) * 512 + j0] = lo;
        g_gml[((2 * bp + 1) * Sdim + s0) * 512 + j0] = hi;
        up2(a01, lo, hi);
        g_gml[((2 * bp + 0) * Sdim + s0 + 1) * 512 + j0] = lo;
        g_gml[((2 * bp + 1) * Sdim + s0 + 1) * 512 + j0] = hi;
        up2(a10, lo, hi);
        g_gml[((2 * bp + 0) * Sdim + s0) * 512 + j1] = lo;
        g_gml[((2 * bp + 1) * Sdim + s0) * 512 + j1] = hi;
        up2(a11, lo, hi);
        g_gml[((2 * bp + 0) * Sdim + s0 + 1) * 512 + j1] = lo;
        g_gml[((2 * bp + 1) * Sdim + s0 + 1) * 512 + j1] = hi;
    }
}

// ---------- main sequential kernel (G=2 rows, 256 threads, 2 j-cols/thread) ----------
#define M_WIHQ 0        // 32768: [q<16][j][4] = Wih[j][4q+r]
#define M_WHHR 32768    // 8192:  [q<4][j][4]  = Whh[j][4q+r]
#define M_WTRQ 40960    // 8192:  [q<32][f][4] = Wtr[f][4q+r]
#define M_WFRQ 49152    // 4096:  [q<16][f][4] = Wfr_m[f][4q+r]
#define M_HR   53248    // 256:  hRow[2][128]
#define M_XC   53504    // 128:  xcRow[2][64]
#define M_CLC  53632    // 128:  clcRow[2][64]
#define M_GT   53760    // 1024: gates[2][512]
#define M_BTR  54784
#define M_BFR  54848
#define M_RED  54912    // 256
#define M_SMF  55168
#define M_SMB  (M_SMF * 4)   // 220,672 B

// one quad-k group: 2 j-cols x 2 rows; 4 loads + 8 ff2, 0 packing
#define FS2(WP0, WP1, AP, STR) do {                                     \
    const ulonglong2 w0_ = *(const ulonglong2*)(WP0);                   \
    const ulonglong2 w1_ = *(const ulonglong2*)(WP1);                   \
    { const ulonglong2 a_ = *(const ulonglong2*)(AP);                   \
      A00 = ff2(w0_.x, a_.x, A00); A00 = ff2(w0_.y, a_.y, A00);         \
      A10 = ff2(w1_.x, a_.x, A10); A10 = ff2(w1_.y, a_.y, A10); }       \
    { const ulonglong2 a_ = *(const ulonglong2*)((AP) + (STR));         \
      A01 = ff2(w0_.x, a_.x, A01); A01 = ff2(w0_.y, a_.y, A01);         \
      A11 = ff2(w1_.x, a_.x, A11); A11 = ff2(w1_.y, a_.y, A11); }       \
} while (0)

__global__ __launch_bounds__(256, 1) void rits_main(
    const float* __restrict__ x, const float* __restrict__ m,
    const float* __restrict__ Wtr, const float* __restrict__ btr,
    const float* __restrict__ Wfr, const float* __restrict__ bfr,
    const float* __restrict__ Wih, const float* __restrict__ Whh,
    float* __restrict__ out)
{
    extern __shared__ float sm[];
    const int t = threadIdx.x;
    const int b0 = blockIdx.x * 2;

    for (int i = t; i < 32768; i += 256) { const int r = i & 3, j = (i >> 2) & 511, q = i >> 11; sm[M_WIHQ + i] = Wih[j * 128 + 4 * q + r]; }
    for (int i = t; i < 8192; i += 256)  { const int r = i & 3, j = (i >> 2) & 511, q = i >> 11; sm[M_WHHR + i] = Whh[j * 128 + 4 * q + r]; }
    for (int i = t; i < 8192; i += 256)  { const int r = i & 3, f = (i >> 2) & 63, q = i >> 8; sm[M_WTRQ + i] = Wtr[f * 128 + 4 * q + r]; }
    for (int i = t; i < 4096; i += 256)  { const int r = i & 3, f = (i >> 2) & 63, q = i >> 8; const int k = 4 * q + r; sm[M_WFRQ + i] = (k == f) ? 0.f : Wfr[f * 64 + k]; }
    if (t < 64) { sm[M_BTR + t] = btr[t]; sm[M_BFR + t] = bfr[t]; }
    for (int i = t; i < 256; i += 256) sm[M_HR + i] = 0.f;
    float c_reg = 0.f, loss = 0.f;

    const int rE = t >> 6, fE = t & 63;     // C/D/E role (t < 128): row, feature
    const int j0 = t, j1 = t + 256;         // F role: two gate columns
    const int rG = t >> 7, jG = t & 127;    // G role: one LSTM state

    // prologue prefetch (s = 0)
    float cx = 0.f, cm = 0.f, cbeta = 0.f;
    if (t < 128) {
        const size_t idxP = ((size_t)(b0 + rE) * Sdim) * Fdim + fE;
        cx = x[idxP]; cm = m[idxP]; cbeta = g_beta[idxP];
    }
    float cgml[4];
    cgml[0] = g_gml[((size_t)(b0 + 0) * Sdim) * 512 + j0];
    cgml[1] = g_gml[((size_t)(b0 + 1) * Sdim) * 512 + j0];
    cgml[2] = g_gml[((size_t)(b0 + 0) * Sdim) * 512 + j1];
    cgml[3] = g_gml[((size_t)(b0 + 1) * Sdim) * 512 + j1];
    __syncthreads();

    for (int s = 0; s < Sdim; ++s) {
        const int sn = (s < Sdim - 1) ? s + 1 : s;
        // prefetch: gamma_h(s+1) for G; next-step x/m/beta/gml
        const float ghv = g_gh[((size_t)(b0 + rG) * Sdim + sn) * Hdim + jG];
        float nx = 0.f, nm = 0.f, nbeta = 0.f, cInv = 0.f;
        if (t < 128) {
            cInv = g_invDenom[s];
            const size_t idxN = ((size_t)(b0 + rE) * Sdim + sn) * Fdim + fE;
            nx = x[idxN]; nm = m[idxN]; nbeta = g_beta[idxN];
        }
        float ngml[4];
        ngml[0] = g_gml[((size_t)(b0 + 0) * Sdim + sn) * 512 + j0];
        ngml[1] = g_gml[((size_t)(b0 + 1) * Sdim + sn) * 512 + j0];
        ngml[2] = g_gml[((size_t)(b0 + 0) * Sdim + sn) * 512 + j1];
        ngml[3] = g_gml[((size_t)(b0 + 1) * Sdim + sn) * 512 + j1];

        // C: xl_hat = h @ Wtr^T + btr ; xl_c   (t < 128)
        float xh = 0.f;
        if (t < 128) {
            u64 acc = 0ULL;
            const float* hr = sm + M_HR + rE * 128;
#pragma unroll 8
            for (int q = 0; q < 32; ++q) {
                const ulonglong2 w = *(const ulonglong2*)(sm + M_WTRQ + (q * 64 + fE) * 4);
                const ulonglong2 a = *(const ulonglong2*)(hr + 4 * q);
                acc = ff2(w.x, a.x, acc); acc = ff2(w.y, a.y, acc);
            }
            float lo, hi; up2(acc, lo, hi);
            xh = sm[M_BTR + fE] + lo + hi;
            sm[M_XC + rE * 64 + fE] = cm * cx + (1.f - cm) * xh;
        }
        __syncthreads();

        // D+E: zl_hat, cl_hat, cl_c, output, loss   (t < 128)
        if (t < 128) {
            u64 acc = 0ULL;
            const float* xr = sm + M_XC + rE * 64;
#pragma unroll
            for (int q = 0; q < 16; ++q) {
                const ulonglong2 w = *(const ulonglong2*)(sm + M_WFRQ + (q * 64 + fE) * 4);
                const ulonglong2 a = *(const ulonglong2*)(xr + 4 * q);
                acc = ff2(w.x, a.x, acc); acc = ff2(w.y, a.y, acc);
            }
            float lo, hi; up2(acc, lo, hi);
            const float zh = sm[M_BFR + fE] + lo + hi;
            const float ch = cbeta * zh + (1.f - cbeta) * xh;
            const float cc = cm * cx + (1.f - cm) * ch;
            sm[M_CLC + rE * 64 + fE] = cc;
            out[((size_t)(b0 + rE) * Sdim + s) * Fdim + fE] = cc;
            const float d1 = cx - xh, d2 = cx - zh, d3 = cx - ch;
            loss += cm * (d1 * d1 + d2 * d2 + d3 * d3) * cInv;
        }
        __syncthreads();

        // F: gates = gml + clc @ WihClc^T + h @ Whh^T   (all 256 threads, 2 j each)
        {
            u64 A00 = 0ULL, A01 = 0ULL, A10 = 0ULL, A11 = 0ULL;
#pragma unroll
            for (int q = 0; q < 16; ++q)
                FS2(sm + M_WIHQ + (q * 512 + j0) * 4,
                    sm + M_WIHQ + (q * 512 + j1) * 4,
                    sm + M_CLC + 4 * q, 64);
#pragma unroll
            for (int q = 0; q < 4; ++q)
                FS2(sm + M_WHHR + (q * 512 + j0) * 4,
                    sm + M_WHHR + (q * 512 + j1) * 4,
                    sm + M_HR + 4 * q, 128);
#pragma unroll 7
            for (int q = 0; q < KQ; ++q)
                FS2(g_WhhQ + ((size_t)q * 512 + j0) * 4,
                    g_WhhQ + ((size_t)q * 512 + j1) * 4,
                    sm + M_HR + 16 + 4 * q, 128);
            float lo, hi;
            up2(A00, lo, hi); sm[M_GT + 0 * 512 + j0] = lo + hi + cgml[0];
            up2(A01, lo, hi); sm[M_GT + 1 * 512 + j0] = lo + hi + cgml[1];
            up2(A10, lo, hi); sm[M_GT + 0 * 512 + j1] = lo + hi + cgml[2];
            up2(A11, lo, hi); sm[M_GT + 1 * 512 + j1] = lo + hi + cgml[3];
        }
        __syncthreads();

        // G: LSTM update + apply gamma_h(s+1)   (1 state per thread)
        {
            const float* gg = sm + M_GT + rG * 512;
            const float iv = sigf(gg[jG]);
            const float fv = sigf(gg[128 + jG]);
            const float gv = tanhf(gg[256 + jG]);
            const float ov = sigf(gg[384 + jG]);
            c_reg = fv * c_reg + iv * gv;
            sm[M_HR + rG * 128 + jG] = ov * tanhf(c_reg) * ghv;
        }
        __syncthreads();

        cx = nx; cm = nm; cbeta = nbeta;
#pragma unroll
        for (int r = 0; r < 4; ++r) cgml[r] = ngml[r];
    }

    sm[M_RED + t] = loss;
    __syncthreads();
    for (int off = 128; off > 0; off >>= 1) { if (t < off) sm[M_RED + t] += sm[M_RED + t + off]; __syncthreads(); }
    if (t == 0) g_lossPartial[blockIdx.x] = sm[M_RED];
}

__global__ void rits_loss_final(float* __restrict__ out, int out_size) {
    __shared__ float red[NBLK];
    const int t = threadIdx.x;
    red[t] = g_lossPartial[t];
    __syncthreads();
    for (int off = NBLK / 2; off > 0; off >>= 1) { if (t < off) red[t] += red[t + off]; __syncthreads(); }
    const long long bsf = (long long)Bdim * Sdim * Fdim;
    if (t == 0 && (long long)out_size > bsf) out[bsf] = red[0] / (float)Sdim;
}

extern "C" void kernel_launch(void* const* d_in, const int* in_sizes, int n_in,
                              void* d_out, int out_size) {
    const float* x   = (const float*)d_in[0];
    const float* m   = (const float*)d_in[1];
    const float* tt  = (const float*)d_in[2];
    const float* Wdh = (const float*)d_in[3];
    const float* bdh = (const float*)d_in[4];
    const float* Wdm = (const float*)d_in[5];
    const float* bdm = (const float*)d_in[6];
    const float* Wtr = (const float*)d_in[7];
    const float* btr = (const float*)d_in[8];
    const float* Wfr = (const float*)d_in[9];
    const float* bfr = (const float*)d_in[10];
    const float* Wwc = (const float*)d_in[11];
    const float* bwc = (const float*)d_in[12];
    const float* Wih = (const float*)d_in[13];
    const float* Whh = (const float*)d_in[14];
    const float* bih = (const float*)d_in[15];
    const float* bhh = (const float*)d_in[16];
    float* out = (float*)d_out;

    cudaFuncSetAttribute(rits_gml, cudaFuncAttributeMaxDynamicSharedMemorySize, GML_SMF * 4);
    cudaFuncSetAttribute(rits_main, cudaFuncAttributeMaxDynamicSharedMemorySize, M_SMB);

    rits_denom<<<Sdim, 256>>>(m);
    rits_whhq<<<(KQ * 512 * 4 + 255) / 256, 256>>>(Whh);
    rits_gh<<<1024, 256>>>(tt, Wdh, bdh);
    rits_betak<<<1024, 256>>>(tt, m, Wdm, bdm, Wwc, bwc);
    rits_gml<<<512, 256, GML_SMF * 4>>>(m, Wih, bih, bhh);
    rits_main<<<NBLK, 256, M_SMB>>>(x, m, Wtr, btr, Wfr, bfr, Wih, Whh, out);
    rits_loss_final<<<1, NBLK>>>(out, out_size);
}

// round 10
// speedup vs baseline: 1.6517x; 1.1035x over previous
#include <cuda_runtime.h>

#define Bdim 256
#define Sdim 512
#define Fdim 64
#define Hdim 128
#define BS   (Bdim * Sdim)
#define NBLK 128           // 2 batch rows per block
#define KQ   28            // streamed Whh quad groups (k = 16..127)
#define NR   14            // register-resident q-groups of the streamed tail

__device__ float g_invDenom[Sdim];
__device__ float g_lossPartial[NBLK];
__device__ float g_WhhQ[KQ * 512 * 4];            // [(q*512+j)*4+r] = Whh[j][16+4q+r]
__device__ float g_gh[(size_t)BS * Hdim];         // gamma_h
__device__ float g_beta[(size_t)BS * Fdim];       // beta
__device__ float g_gml[(size_t)BS * 512];         // [b][s][j]: ml@WihMask^T + bio

typedef unsigned long long u64;
__device__ __forceinline__ u64 pk2(float lo, float hi) {
    u64 r; asm("mov.b64 %0,{%1,%2};" : "=l"(r) : "r"(__float_as_uint(lo)), "r"(__float_as_uint(hi))); return r;
}
__device__ __forceinline__ void up2(u64 v, float& lo, float& hi) {
    unsigned a, b; asm("mov.b64 {%0,%1},%2;" : "=r"(a), "=r"(b) : "l"(v));
    lo = __uint_as_float(a); hi = __uint_as_float(b);
}
__device__ __forceinline__ u64 ff2(u64 a, u64 b, u64 c) {
    u64 d; asm("fma.rn.f32x2 %0,%1,%2,%3;" : "=l"(d) : "l"(a), "l"(b), "l"(c)); return d;
}
__device__ __forceinline__ float sigf(float v) { return 1.f / (1.f + expf(-v)); }

// ================= fused precompute kernel =================
// blockIdx ranges:  [0,512) denom | [512,736) whhq | [736,1760) gh
//                   [1760,2784) betak | [2784,3808) gml (j-split)
#define PRE_SMF 17152
#define PRE_SMB (PRE_SMF * 4)   // 68,608 B

__global__ __launch_bounds__(256) void rits_pre(
    const float* __restrict__ m,   const float* __restrict__ tt,
    const float* __restrict__ Wdh, const float* __restrict__ bdh,
    const float* __restrict__ Wdm, const float* __restrict__ bdm,
    const float* __restrict__ Wwc, const float* __restrict__ bwc,
    const float* __restrict__ Wih, const float* __restrict__ bih,
    const float* __restrict__ bhh, const float* __restrict__ Whh)
{
    extern __shared__ float sp[];
    const int b = blockIdx.x, t = threadIdx.x;

    if (b < 512) {
        // ---- denom: per-step 1/(sum(m)+1e-5) ----
        float* red = sp;
        const int s = b;
        const float4* p = (const float4*)(m + (size_t)t * Sdim * Fdim + (size_t)s * Fdim);
        float sum = 0.f;
#pragma unroll
        for (int i = 0; i < 16; ++i) { float4 v = p[i]; sum += v.x + v.y + v.z + v.w; }
        red[t] = sum;
        __syncthreads();
        for (int off = 128; off > 0; off >>= 1) { if (t < off) red[t] += red[t + off]; __syncthreads(); }
        if (t == 0) g_invDenom[s] = 1.0f / (red[0] + 1e-5f);
    } else if (b < 736) {
        // ---- whhq: Whh streamed-tail swizzle ----
        const int i = (b - 512) * 256 + t;
        if (i < KQ * 512 * 4) {
            const int r = i & 3, j = (i >> 2) & 511, q = i >> 11;
            g_WhhQ[i] = Whh[j * Hdim + 16 + 4 * q + r];
        }
    } else if (b < 1760) {
        // ---- gamma_h ----
        const int blk = b - 736;
        float* w = sp; float* bb = sp + 8192; float* tl = sp + 8320;  // tl[2][128]
        for (int i = t; i < Fdim * Hdim; i += 256) { const int k = i >> 7, h = i & 127; w[i] = Wdh[h * Fdim + k]; }
        if (t < Hdim) bb[t] = bdh[t];
        const int rr = t >> 7, h = t & 127;
        const size_t base = (size_t)blk * 128;
        float v = 0.f;
        if (t < 128) v = tt[(base + (t >> 6)) * Fdim + (t & 63)];
        __syncthreads();
        for (int it = 0; it < 64; ++it) {
            const size_t rs = base + it * 2;
            if (t < 128) tl[(it & 1) * 128 + t] = v;
            __syncthreads();
            if (t < 128 && it < 63) v = tt[(rs + 2 + (t >> 6)) * Fdim + (t & 63)];
            float a0 = 0.f, a1 = 0.f;
            const float* tlr = tl + (it & 1) * 128 + rr * 64;
#pragma unroll 8
            for (int k = 0; k < Fdim; k += 2) { a0 += tlr[k] * w[k * 128 + h]; a1 += tlr[k + 1] * w[(k + 1) * 128 + h]; }
            g_gh[(rs + rr) * Hdim + h] = expf(-fmaxf(a0 + a1 + bb[h], 0.f));
        }
    } else if (b < 2784) {
        // ---- beta ----
        const int blk = b - 1760;
        float* w = sp;                 // 8192
        float* dwdm = sp + 8192; float* cb = sp + 8256; float* cw = sp + 8320;
        float* gm = sp + 8384;         // [2][256]
        float* ms = sp + 8896;         // [2][256]
        for (int i = t; i < 128 * Fdim; i += 256) { const int k = i >> 6, f = i & 63; w[i] = Wwc[f * 128 + k]; }
        if (t < 64) { dwdm[t] = Wdm[t * Fdim + t]; cb[t] = bdm[t]; cw[t] = bwc[t]; }
        const int r = t >> 6, f = t & 63;
        const size_t base = (size_t)blk * 128;
        float vt = tt[(base + r) * Fdim + f], vm = m[(base + r) * Fdim + f];
        __syncthreads();
        for (int it = 0; it < 32; ++it) {
            const size_t rs = base + it * 4 + r;
            const int bf = it & 1;
            gm[bf * 256 + t] = expf(-fmaxf(vt * dwdm[f] + cb[f], 0.f)); ms[bf * 256 + t] = vm;
            __syncthreads();
            if (it < 31) { vt = tt[(rs + 4) * Fdim + f]; vm = m[(rs + 4) * Fdim + f]; }
            float a0 = cw[f], a1 = 0.f;
            const float* gr = gm + bf * 256 + r * 64; const float* mr = ms + bf * 256 + r * 64;
#pragma unroll 8
            for (int k = 0; k < 64; ++k) { a0 += gr[k] * w[k * 64 + f]; a1 += mr[k] * w[(64 + k) * 64 + f]; }
            g_beta[rs * Fdim + f] = a0 + a1;
        }
    } else {
        // ---- gml (j-split): 512 p-blocks x 2 j-halves ----
        const int pb = b - 2784;
        const int jh = pb & 1, pblk = pb >> 1;
        float* WT  = sp;            // [k2<32][jl<256][2] = Wih[jh*256+jl][64+2k2+r]
        float* BIO = sp + 16384;    // 256
        float* MLP = sp + 16640;    // [2 buf][2 p][128]
        for (int i = t; i < 16384; i += 256) {
            const int r = i & 1, jl = (i >> 1) & 255, k2 = i >> 9;
            WT[i] = Wih[(jh * 256 + jl) * 128 + 64 + 2 * k2 + r];
        }
        { const int j = jh * 256 + t; BIO[t] = bih[j] + bhh[j]; }
        const int pr = t >> 7, gq = (t >> 6) & 1, f = t & 63;
        const size_t base = (size_t)pblk * 128;
        float v;
        { const size_t p0 = base; const size_t bp = p0 >> 9; const int s0 = (int)(p0 & 511);
          v = m[((2 * bp + gq) * Sdim + s0 + pr) * Fdim + f]; }
        __syncthreads();
        for (int it = 0; it < 64; ++it) {
            const size_t p0 = base + 2 * it; const size_t bp = p0 >> 9; const int s0 = (int)(p0 & 511);
            float* B = MLP + (it & 1) * 256;
            B[pr * 128 + 2 * f + gq] = v;
            __syncthreads();
            if (it < 63) { const size_t pn = base + 2 * (it + 1); const size_t bpn = pn >> 9; const int sn0 = (int)(pn & 511);
                v = m[((2 * bpn + gq) * Sdim + sn0 + pr) * Fdim + f]; }
            const float bj = BIO[t];
            u64 a0 = pk2(bj, bj), a1 = pk2(bj, bj);
            const float* B0 = B; const float* B1 = B + 128;
#pragma unroll 8
            for (int k2 = 0; k2 < 32; ++k2) {
                const float2 w0 = *(const float2*)(WT + (k2 * 256 + t) * 2);
                const ulonglong2 q0 = *(const ulonglong2*)(B0 + 4 * k2);
                const ulonglong2 q1 = *(const ulonglong2*)(B1 + 4 * k2);
                const u64 wx = pk2(w0.x, w0.x), wy = pk2(w0.y, w0.y);
                a0 = ff2(wx, q0.x, a0); a0 = ff2(wy, q0.y, a0);
                a1 = ff2(wx, q1.x, a1); a1 = ff2(wy, q1.y, a1);
            }
            const int j = jh * 256 + t;
            float lo, hi;
            up2(a0, lo, hi);
            g_gml[((2 * bp + 0) * Sdim + s0) * 512 + j] = lo;
            g_gml[((2 * bp + 1) * Sdim + s0) * 512 + j] = hi;
            up2(a1, lo, hi);
            g_gml[((2 * bp + 0) * Sdim + s0 + 1) * 512 + j] = lo;
            g_gml[((2 * bp + 1) * Sdim + s0 + 1) * 512 + j] = hi;
        }
    }
}

// ================= main sequential kernel =================
#define M_WIHQ 0        // 32768: [q<16][j][4] = Wih[j][4q+r]
#define M_WHHR 32768    // 8192:  [q<4][j][4]  = Whh[j][4q+r]
#define M_WTRQ 40960    // 8192:  [q<32][f][4] = Wtr[f][4q+r]
#define M_WFRQ 49152    // 4096:  [q<16][f][4] = Wfr_m[f][4q+r]
#define M_HR   53248    // 256:  hRow[2][128]
#define M_XC   53504    // 128
#define M_CLC  53632    // 128
#define M_GT   53760    // 1024
#define M_BTR  54784
#define M_BFR  54848
#define M_RED  54912    // 256
#define M_SMF  55168
#define M_SMB  (M_SMF * 4)   // 220,672 B

// 2 j-cols x 2 rows from smem/global weight pointer
#define FS2(WP0, WP1, AP, STR) do {                                     \
    const ulonglong2 w0_ = *(const ulonglong2*)(WP0);                   \
    const ulonglong2 w1_ = *(const ulonglong2*)(WP1);                   \
    { const ulonglong2 a_ = *(const ulonglong2*)(AP);                   \
      A00 = ff2(w0_.x, a_.x, A00); A00 = ff2(w0_.y, a_.y, A00);         \
      A10 = ff2(w1_.x, a_.x, A10); A10 = ff2(w1_.y, a_.y, A10); }       \
    { const ulonglong2 a_ = *(const ulonglong2*)((AP) + (STR));         \
      A01 = ff2(w0_.x, a_.x, A01); A01 = ff2(w0_.y, a_.y, A01);         \
      A11 = ff2(w1_.x, a_.x, A11); A11 = ff2(w1_.y, a_.y, A11); }       \
} while (0)

__global__ __launch_bounds__(256, 1) void rits_main(
    const float* __restrict__ x, const float* __restrict__ m,
    const float* __restrict__ Wtr, const float* __restrict__ btr,
    const float* __restrict__ Wfr, const float* __restrict__ bfr,
    const float* __restrict__ Wih, const float* __restrict__ Whh,
    float* __restrict__ out)
{
    extern __shared__ float sm[];
    const int t = threadIdx.x;
    const int b0 = blockIdx.x * 2;

    for (int i = t; i < 32768; i += 256) { const int r = i & 3, j = (i >> 2) & 511, q = i >> 11; sm[M_WIHQ + i] = Wih[j * 128 + 4 * q + r]; }
    for (int i = t; i < 8192; i += 256)  { const int r = i & 3, j = (i >> 2) & 511, q = i >> 11; sm[M_WHHR + i] = Whh[j * 128 + 4 * q + r]; }
    for (int i = t; i < 8192; i += 256)  { const int r = i & 3, f = (i >> 2) & 63, q = i >> 8; sm[M_WTRQ + i] = Wtr[f * 128 + 4 * q + r]; }
    for (int i = t; i < 4096; i += 256)  { const int r = i & 3, f = (i >> 2) & 63, q = i >> 8; const int k = 4 * q + r; sm[M_WFRQ + i] = (k == f) ? 0.f : Wfr[f * 64 + k]; }
    if (t < 64) { sm[M_BTR + t] = btr[t]; sm[M_BFR + t] = bfr[t]; }
    sm[M_HR + t] = 0.f;
    float c_reg = 0.f, loss = 0.f;

    const int rE = t >> 6, fE = t & 63;     // C/D/E role (t < 128)
    const int j0 = t, j1 = t + 256;         // F role: two gate columns
    const int rG = t >> 7, jG = t & 127;    // G role

    // register-resident slice of the streamed Whh tail (q = 0..NR-1, k = 16..16+4NR-1)
    u64 rw[NR * 4];
#pragma unroll
    for (int q = 0; q < NR; ++q) {
        const ulonglong2 a = *(const ulonglong2*)(g_WhhQ + ((size_t)q * 512 + j0) * 4);
        const ulonglong2 bq = *(const ulonglong2*)(g_WhhQ + ((size_t)q * 512 + j1) * 4);
        rw[4 * q] = a.x; rw[4 * q + 1] = a.y; rw[4 * q + 2] = bq.x; rw[4 * q + 3] = bq.y;
    }

    // prologue prefetch (s = 0)
    float cx = 0.f, cm = 0.f, cbeta = 0.f;
    if (t < 128) {
        const size_t idxP = ((size_t)(b0 + rE) * Sdim) * Fdim + fE;
        cx = x[idxP]; cm = m[idxP]; cbeta = g_beta[idxP];
    }
    float cgml[4];
    cgml[0] = g_gml[((size_t)(b0 + 0) * Sdim) * 512 + j0];
    cgml[1] = g_gml[((size_t)(b0 + 1) * Sdim) * 512 + j0];
    cgml[2] = g_gml[((size_t)(b0 + 0) * Sdim) * 512 + j1];
    cgml[3] = g_gml[((size_t)(b0 + 1) * Sdim) * 512 + j1];
    __syncthreads();

    for (int s = 0; s < Sdim; ++s) {
        const int sn = (s < Sdim - 1) ? s + 1 : s;
        const float ghv = g_gh[((size_t)(b0 + rG) * Sdim + sn) * Hdim + jG];
        float nx = 0.f, nm = 0.f, nbeta = 0.f, cInv = 0.f;
        if (t < 128) {
            cInv = g_invDenom[s];
            const size_t idxN = ((size_t)(b0 + rE) * Sdim + sn) * Fdim + fE;
            nx = x[idxN]; nm = m[idxN]; nbeta = g_beta[idxN];
        }
        float ngml[4];
        ngml[0] = g_gml[((size_t)(b0 + 0) * Sdim + sn) * 512 + j0];
        ngml[1] = g_gml[((size_t)(b0 + 1) * Sdim + sn) * 512 + j0];
        ngml[2] = g_gml[((size_t)(b0 + 0) * Sdim + sn) * 512 + j1];
        ngml[3] = g_gml[((size_t)(b0 + 1) * Sdim + sn) * 512 + j1];

        // C: xl_hat = h @ Wtr^T + btr ; xl_c
        float xh = 0.f;
        if (t < 128) {
            u64 acc = 0ULL;
            const float* hr = sm + M_HR + rE * 128;
#pragma unroll 8
            for (int q = 0; q < 32; ++q) {
                const ulonglong2 w = *(const ulonglong2*)(sm + M_WTRQ + (q * 64 + fE) * 4);
                const ulonglong2 a = *(const ulonglong2*)(hr + 4 * q);
                acc = ff2(w.x, a.x, acc); acc = ff2(w.y, a.y, acc);
            }
            float lo, hi; up2(acc, lo, hi);
            xh = sm[M_BTR + fE] + lo + hi;
            sm[M_XC + rE * 64 + fE] = cm * cx + (1.f - cm) * xh;
        }
        __syncthreads();

        // D+E: zl_hat, cl_hat, cl_c, output, loss
        if (t < 128) {
            u64 acc = 0ULL;
            const float* xr = sm + M_XC + rE * 64;
#pragma unroll
            for (int q = 0; q < 16; ++q) {
                const ulonglong2 w = *(const ulonglong2*)(sm + M_WFRQ + (q * 64 + fE) * 4);
                const ulonglong2 a = *(const ulonglong2*)(xr + 4 * q);
                acc = ff2(w.x, a.x, acc); acc = ff2(w.y, a.y, acc);
            }
            float lo, hi; up2(acc, lo, hi);
            const float zh = sm[M_BFR + fE] + lo + hi;
            const float ch = cbeta * zh + (1.f - cbeta) * xh;
            const float cc = cm * cx + (1.f - cm) * ch;
            sm[M_CLC + rE * 64 + fE] = cc;
            out[((size_t)(b0 + rE) * Sdim + s) * Fdim + fE] = cc;
            const float d1 = cx - xh, d2 = cx - zh, d3 = cx - ch;
            loss += cm * (d1 * d1 + d2 * d2 + d3 * d3) * cInv;
        }
        __syncthreads();

        // F: gates = gml + clc @ WihClc^T + h @ Whh^T
        {
            u64 A00 = 0ULL, A01 = 0ULL, A10 = 0ULL, A11 = 0ULL;
#pragma unroll
            for (int q = 0; q < 16; ++q)
                FS2(sm + M_WIHQ + (q * 512 + j0) * 4,
                    sm + M_WIHQ + (q * 512 + j1) * 4,
                    sm + M_CLC + 4 * q, 64);
#pragma unroll
            for (int q = 0; q < 4; ++q)
                FS2(sm + M_WHHR + (q * 512 + j0) * 4,
                    sm + M_WHHR + (q * 512 + j1) * 4,
                    sm + M_HR + 4 * q, 128);
            // register-resident k = 16 .. 16+4*NR-1
#pragma unroll
            for (int q = 0; q < NR; ++q) {
                const float* AP = sm + M_HR + 16 + 4 * q;
                { const ulonglong2 a_ = *(const ulonglong2*)(AP);
                  A00 = ff2(rw[4 * q], a_.x, A00); A00 = ff2(rw[4 * q + 1], a_.y, A00);
                  A10 = ff2(rw[4 * q + 2], a_.x, A10); A10 = ff2(rw[4 * q + 3], a_.y, A10); }
                { const ulonglong2 a_ = *(const ulonglong2*)(AP + 128);
                  A01 = ff2(rw[4 * q], a_.x, A01); A01 = ff2(rw[4 * q + 1], a_.y, A01);
                  A11 = ff2(rw[4 * q + 2], a_.x, A11); A11 = ff2(rw[4 * q + 3], a_.y, A11); }
            }
            // streamed k tail
#pragma unroll 7
            for (int q = NR; q < KQ; ++q)
                FS2(g_WhhQ + ((size_t)q * 512 + j0) * 4,
                    g_WhhQ + ((size_t)q * 512 + j1) * 4,
                    sm + M_HR + 16 + 4 * q, 128);
            float lo, hi;
            up2(A00, lo, hi); sm[M_GT + 0 * 512 + j0] = lo + hi + cgml[0];
            up2(A01, lo, hi); sm[M_GT + 1 * 512 + j0] = lo + hi + cgml[1];
            up2(A10, lo, hi); sm[M_GT + 0 * 512 + j1] = lo + hi + cgml[2];
            up2(A11, lo, hi); sm[M_GT + 1 * 512 + j1] = lo + hi + cgml[3];
        }
        __syncthreads();

        // G: LSTM update + apply gamma_h(s+1)
        {
            const float* gg = sm + M_GT + rG * 512;
            const float iv = sigf(gg[jG]);
            const float fv = sigf(gg[128 + jG]);
            const float gv = tanhf(gg[256 + jG]);
            const float ov = sigf(gg[384 + jG]);
            c_reg = fv * c_reg + iv * gv;
            sm[M_HR + rG * 128 + jG] = ov * tanhf(c_reg) * ghv;
        }
        __syncthreads();

        cx = nx; cm = nm; cbeta = nbeta;
#pragma unroll
        for (int r = 0; r < 4; ++r) cgml[r] = ngml[r];
    }

    sm[M_RED + t] = loss;
    __syncthreads();
    for (int off = 128; off > 0; off >>= 1) { if (t < off) sm[M_RED + t] += sm[M_RED + t + off]; __syncthreads(); }
    if (t == 0) g_lossPartial[blockIdx.x] = sm[M_RED];
}

__global__ void rits_loss_final(float* __restrict__ out, int out_size) {
    __shared__ float red[NBLK];
    const int t = threadIdx.x;
    red[t] = g_lossPartial[t];
    __syncthreads();
    for (int off = NBLK / 2; off > 0; off >>= 1) { if (t < off) red[t] += red[t + off]; __syncthreads(); }
    const long long bsf = (long long)Bdim * Sdim * Fdim;
    if (t == 0 && (long long)out_size > bsf) out[bsf] = red[0] / (float)Sdim;
}

extern "C" void kernel_launch(void* const* d_in, const int* in_sizes, int n_in,
                              void* d_out, int out_size) {
    const float* x   = (const float*)d_in[0];
    const float* m   = (const float*)d_in[1];
    const float* tt  = (const float*)d_in[2];
    const float* Wdh = (const float*)d_in[3];
    const float* bdh = (const float*)d_in[4];
    const float* Wdm = (const float*)d_in[5];
    const float* bdm = (const float*)d_in[6];
    const float* Wtr = (const float*)d_in[7];
    const float* btr = (const float*)d_in[8];
    const float* Wfr = (const float*)d_in[9];
    const float* bfr = (const float*)d_in[10];
    const float* Wwc = (const float*)d_in[11];
    const float* bwc = (const float*)d_in[12];
    const float* Wih = (const float*)d_in[13];
    const float* Whh = (const float*)d_in[14];
    const float* bih = (const float*)d_in[15];
    const float* bhh = (const float*)d_in[16];
    float* out = (float*)d_out;

    cudaFuncSetAttribute(rits_pre, cudaFuncAttributeMaxDynamicSharedMemorySize, PRE_SMB);
    cudaFuncSetAttribute(rits_main, cudaFuncAttributeMaxDynamicSharedMemorySize, M_SMB);

    rits_pre<<<3808, 256, PRE_SMB>>>(m, tt, Wdh, bdh, Wdm, bdm, Wwc, bwc, Wih, bih, bhh, Whh);
    rits_main<<<NBLK, 256, M_SMB>>>(x, m, Wtr, btr, Wfr, bfr, Wih, Whh, out);
    rits_loss_final<<<1, NBLK>>>(out, out_size);
}